// round 13
// baseline (speedup 1.0000x reference)
#include <cuda_runtime.h>
#include <cuda_bf16.h>
#include <math.h>
#include <stdint.h>
#include <stddef.h>

// ---------------- problem constants ----------------
#define BWIN   4096
#define NTOK   49
#define DIMC   256
#define NH     8
#define HD     32
#define TDIM   768
#define MROWS  (BWIN * NTOK)   // 200704

// ---------------- scratch ----------------
__device__ float g_qkv[(size_t)MROWS * TDIM];
__device__ __nv_bfloat16 g_xhi[(size_t)MROWS * DIMC];
__device__ __nv_bfloat16 g_xlo[(size_t)MROWS * DIMC];
__device__ __nv_bfloat16 g_aohi[(size_t)MROWS * DIMC];
__device__ __nv_bfloat16 g_aolo[(size_t)MROWS * DIMC];
__device__ __nv_bfloat16 g_wqhi[TDIM * DIMC];
__device__ __nv_bfloat16 g_wqlo[TDIM * DIMC];
__device__ __nv_bfloat16 g_wphi[DIMC * DIMC];
__device__ __nv_bfloat16 g_wplo[DIMC * DIMC];
__device__ float g_bias768[TDIM];
__device__ float g_cbias[64 * NH * 49 * 52];

__device__ __forceinline__ uint32_t pk(__nv_bfloat16 a, __nv_bfloat16 b) {
    return (uint32_t)__bfloat16_as_ushort(a) | ((uint32_t)__bfloat16_as_ushort(b) << 16);
}

__device__ __forceinline__ void split_store(const float* __restrict__ src,
                                            __nv_bfloat16* __restrict__ hi,
                                            __nv_bfloat16* __restrict__ lo, int i) {
    float4 v = ((const float4*)src)[i];
    __nv_bfloat16 hx = __float2bfloat16(v.x), hy = __float2bfloat16(v.y);
    __nv_bfloat16 hz = __float2bfloat16(v.z), hw = __float2bfloat16(v.w);
    uint2 H = make_uint2(pk(hx, hy), pk(hz, hw));
    uint2 L = make_uint2(
        pk(__float2bfloat16(v.x - __bfloat162float(hx)),
           __float2bfloat16(v.y - __bfloat162float(hy))),
        pk(__float2bfloat16(v.z - __bfloat162float(hz)),
           __float2bfloat16(v.w - __bfloat162float(hw))));
    ((uint2*)hi)[i] = H;
    ((uint2*)lo)[i] = L;
}

// ---------------- merged setup: split x/wq/wp + bias fill ----------------
#define NX4  (MROWS * DIMC / 4)
#define NWQ4 (TDIM * DIMC / 4)
#define NWP4 (DIMC * DIMC / 4)
#define NTOT4 (NX4 + NWQ4 + NWP4)

__global__ void split_all(const float* __restrict__ x,
                          const float* __restrict__ wq,
                          const float* __restrict__ wp,
                          const float* __restrict__ q_bias,
                          const float* __restrict__ v_bias) {
    int i = blockIdx.x * 256 + threadIdx.x;
    if (i < TDIM) {
        float bv;
        if (i < 256)      bv = q_bias[i];
        else if (i < 512) bv = 0.f;
        else              bv = v_bias[i - 512];
        g_bias768[i] = bv;
    }
    if (i < NX4) {
        split_store(x, g_xhi, g_xlo, i);
    } else if (i < NX4 + NWQ4) {
        split_store(wq, g_wqhi, g_wqlo, i - NX4);
    } else if (i < NTOT4) {
        split_store(wp, g_wphi, g_wplo, i - NX4 - NWQ4);
    }
}

// ---------------- merged CPB MLP + combined bias (per (wm,h) block) ----------
__global__ void cbias_comb(const int* __restrict__ rpi,
                           const float* __restrict__ mask,
                           const float* __restrict__ coords,
                           const float* __restrict__ w1,
                           const float* __restrict__ b1,
                           const float* __restrict__ w2) {
    __shared__ float th[169];
    int blk = blockIdx.x;            // wm*8 + h
    int wm = blk >> 3, h = blk & 7;
    int tid = threadIdx.x;
    if (tid < 169) {
        float c0 = coords[tid * 2 + 0];
        float c1 = coords[tid * 2 + 1];
        const float* w2h = w2 + h * 512;
        float s = 0.f;
        for (int k = 0; k < 512; ++k) {
            float v = fmaf(c0, w1[2 * k], fmaf(c1, w1[2 * k + 1], b1[k]));
            s = fmaf(fmaxf(v, 0.f), w2h[k], s);
        }
        th[tid] = s;
    }
    __syncthreads();
    float* dst = g_cbias + (size_t)blk * (49 * 52);
    const float* m = mask + wm * (NTOK * NTOK);
    for (int idx = tid; idx < 49 * 52; idx += 256) {
        int i = idx / 52, j = idx % 52;
        float v = 0.f;
        if (j < 49) {
            float t = th[rpi[i * NTOK + j]];
            v = 16.f / (1.f + expf(-t)) + m[i * NTOK + j];
        }
        dst[idx] = v;
    }
}

// ================= bf16x3 GEMM, 512 threads (4 warps/SMSP), KC=64 ===========
#define KC     64
#define ROWB   144
#define MATB   (128 * ROWB)
#define STAGEB (4 * MATB)
#define NSTG   3
#define GSMEM  (NSTG * STAGEB)

__device__ __forceinline__ uint32_t s2u(const void* p) {
    uint32_t a;
    asm("{ .reg .u64 t; cvta.to.shared.u64 t, %1; cvt.u32.u64 %0, t; }"
        : "=r"(a) : "l"(p));
    return a;
}

#define CPA16(saddr, gaddr)                                                   \
    asm volatile("cp.async.cg.shared.global [%0], [%1], 16;"                  \
                 :: "r"(saddr), "l"(gaddr))
#define CPA_COMMIT() asm volatile("cp.async.commit_group;" ::: "memory")
#define CPA_WAIT1()  asm volatile("cp.async.wait_group 1;" ::: "memory")

#define LDSM4(r0, r1, r2, r3, a)                                              \
    asm volatile("ldmatrix.sync.aligned.m8n8.x4.shared.b16 {%0,%1,%2,%3}, [%4];" \
                 : "=r"(r0), "=r"(r1), "=r"(r2), "=r"(r3) : "r"(a))

#define MMA16816(c, a, b)                                                     \
    asm volatile(                                                             \
        "mma.sync.aligned.m16n8k16.row.col.f32.bf16.bf16.f32 "                \
        "{%0,%1,%2,%3},{%4,%5,%6,%7},{%8,%9},{%0,%1,%2,%3};"                  \
        : "+f"((c)[0]), "+f"((c)[1]), "+f"((c)[2]), "+f"((c)[3])              \
        : "r"((a)[0]), "r"((a)[1]), "r"((a)[2]), "r"((a)[3]),                 \
          "r"((b)[0]), "r"((b)[1]))

__global__ __launch_bounds__(512)
void gemm_bf16x3(const __nv_bfloat16* __restrict__ Ahi,
                 const __nv_bfloat16* __restrict__ Alo,
                 const __nv_bfloat16* __restrict__ Whi,
                 const __nv_bfloat16* __restrict__ Wlo,
                 const float* __restrict__ bias, float* __restrict__ C,
                 int N, int K) {
    extern __shared__ char sm[];
    uint32_t smb = s2u(sm);

    int tid = threadIdx.x, lane = tid & 31, wid = tid >> 5;
    int warpM = wid & 3;
    int warpN = wid >> 2;
    size_t rowBlk = (size_t)blockIdx.y * 128;
    int colBlk = blockIdx.x * 128;

    float acc[2][4][4];
#pragma unroll
    for (int mt = 0; mt < 2; ++mt)
#pragma unroll
        for (int nt = 0; nt < 4; ++nt)
#pragma unroll
            for (int u = 0; u < 4; ++u) acc[mt][nt][u] = 0.f;

    const __nv_bfloat16* gA[2] = {Ahi, Alo};
    const __nv_bfloat16* gW[2] = {Whi, Wlo};

    const int NCH = K >> 6;

    int g = lane >> 3, l7 = lane & 7;
    uint32_t aOff = (uint32_t)(warpM * 32 + (g & 1) * 8 + l7) * ROWB + (uint32_t)(g >> 1) * 16;
    uint32_t wOff = (uint32_t)(warpN * 32 + (g >> 1) * 8 + l7) * ROWB + (uint32_t)(g & 1) * 16;

#define ISSUE_CHUNK(ch)                                                       \
    do {                                                                      \
        uint32_t stg_ = smb + (uint32_t)((ch) % 3) * STAGEB;                  \
        int koff_ = (ch) * KC;                                                \
        _Pragma("unroll")                                                     \
        for (int i_ = 0; i_ < 2; ++i_) {                                      \
            int slot_ = tid + i_ * 512;                                       \
            int lr_ = slot_ >> 3, lc_ = slot_ & 7;                            \
            uint32_t so_ = stg_ + (uint32_t)lr_ * ROWB + (uint32_t)lc_ * 16;  \
            size_t ge_ = (rowBlk + lr_) * (size_t)K + koff_ + lc_ * 8;        \
            size_t gw_ = (size_t)(colBlk + lr_) * K + koff_ + lc_ * 8;        \
            CPA16(so_,            gA[0] + ge_);                               \
            CPA16(so_ + MATB,     gA[1] + ge_);                               \
            CPA16(so_ + 2 * MATB, gW[0] + gw_);                               \
            CPA16(so_ + 3 * MATB, gW[1] + gw_);                               \
        }                                                                     \
    } while (0)

    uint32_t ah[2][2][4], al[2][2][4], wh[2][4][2], wl[2][4][2];

#define LOAD_FRAG(buf, stg, kb)                                               \
    do {                                                                      \
        _Pragma("unroll")                                                     \
        for (int mt_ = 0; mt_ < 2; ++mt_) {                                   \
            uint32_t ad_ = (stg) + aOff + (uint32_t)mt_ * (16 * ROWB) + (kb); \
            LDSM4(ah[buf][mt_][0], ah[buf][mt_][1], ah[buf][mt_][2], ah[buf][mt_][3], ad_); \
            LDSM4(al[buf][mt_][0], al[buf][mt_][1], al[buf][mt_][2], al[buf][mt_][3], ad_ + MATB); \
        }                                                                     \
        _Pragma("unroll")                                                     \
        for (int p_ = 0; p_ < 2; ++p_) {                                      \
            uint32_t wd_ = (stg) + 2 * MATB + wOff + (uint32_t)p_ * (16 * ROWB) + (kb); \
            uint32_t t0_, t1_, t2_, t3_;                                      \
            LDSM4(t0_, t1_, t2_, t3_, wd_);                                   \
            wh[buf][2 * p_][0] = t0_; wh[buf][2 * p_][1] = t1_;               \
            wh[buf][2 * p_ + 1][0] = t2_; wh[buf][2 * p_ + 1][1] = t3_;       \
            LDSM4(t0_, t1_, t2_, t3_, wd_ + MATB);                            \
            wl[buf][2 * p_][0] = t0_; wl[buf][2 * p_][1] = t1_;               \
            wl[buf][2 * p_ + 1][0] = t2_; wl[buf][2 * p_ + 1][1] = t3_;       \
        }                                                                     \
    } while (0)

#define MMA_STEP(buf)                                                         \
    do {                                                                      \
        _Pragma("unroll")                                                     \
        for (int mt_ = 0; mt_ < 2; ++mt_)                                     \
            _Pragma("unroll")                                                 \
            for (int nt_ = 0; nt_ < 4; ++nt_) {                               \
                MMA16816(acc[mt_][nt_], ah[buf][mt_], wh[buf][nt_]);          \
                MMA16816(acc[mt_][nt_], ah[buf][mt_], wl[buf][nt_]);          \
                MMA16816(acc[mt_][nt_], al[buf][mt_], wh[buf][nt_]);          \
            }                                                                 \
    } while (0)

    ISSUE_CHUNK(0); CPA_COMMIT();
    ISSUE_CHUNK(1); CPA_COMMIT();

    for (int ch = 0; ch < NCH; ++ch) {
        CPA_WAIT1();
        __syncthreads();
        if (ch + 2 < NCH) ISSUE_CHUNK(ch + 2);
        CPA_COMMIT();

        uint32_t stg = smb + (uint32_t)(ch % 3) * STAGEB;
        LOAD_FRAG(0, stg, 0u);
#pragma unroll
        for (int ks = 0; ks < 4; ++ks) {
            if (ks < 3) LOAD_FRAG((ks + 1) & 1, stg, (uint32_t)(ks + 1) * 32);
            MMA_STEP(ks & 1);
        }
    }

#pragma unroll
    for (int nt = 0; nt < 4; ++nt) {
        int col = colBlk + warpN * 32 + nt * 8 + (lane & 3) * 2;
        float2 bv = *(const float2*)(bias + col);
#pragma unroll
        for (int mt = 0; mt < 2; ++mt) {
            size_t row0 = rowBlk + warpM * 32 + mt * 16 + (lane >> 2);
            float2 o0, o1;
            o0.x = acc[mt][nt][0] + bv.x; o0.y = acc[mt][nt][1] + bv.y;
            o1.x = acc[mt][nt][2] + bv.x; o1.y = acc[mt][nt][3] + bv.y;
            *(float2*)(C + row0 * (size_t)N + col)       = o0;
            *(float2*)(C + (row0 + 8) * (size_t)N + col) = o1;
        }
    }
}

// ================= attention: conflict-free QK + float4 AV + cbias preload ==
#define SAT 56   // sattn row stride (floats), 16B-aligned float4 at j%4==0

__global__ __launch_bounds__(256)
void attn_kernel(const float* __restrict__ logit_scale) {
    __shared__ float sq[52][36];
    __shared__ float sk[52][36];
    __shared__ float sv[52][36];
    __shared__ float sattn[52][SAT];

    int blk = blockIdx.x;
    int b = blk >> 3;
    int h = blk & 7;
    int tid = threadIdx.x;
    int wid = tid >> 5, lane = tid & 31;

    // load q,k,v
    for (int idx = tid; idx < NTOK * 8; idx += 256) {
        int n = idx >> 3, d4 = (idx & 7) << 2;
        size_t base = ((size_t)b * NTOK + n) * TDIM + h * HD + d4;
        *(float4*)&sq[n][d4] = *(const float4*)(g_qkv + base);
        *(float4*)&sk[n][d4] = *(const float4*)(g_qkv + base + 256);
        *(float4*)&sv[n][d4] = *(const float4*)(g_qkv + base + 512);
    }
    // preload cbias into sattn cols 0..51 (cols 49..51 are zero in g_cbias)
    {
        const float* cb = g_cbias + ((size_t)((b & 63) * NH + h)) * (49 * 52);
        for (int idx = tid; idx < NTOK * 13; idx += 256) {
            int i = idx / 13, c4 = (idx % 13) * 4;
            *(float4*)&sattn[i][c4] = *(const float4*)(cb + i * 52 + c4);
        }
    }
    // zero pads
    if (tid < 108) {                       // q/k/v rows 49..51
        int r = 49 + tid / 36, c = tid % 36;
        sq[r][c] = 0.f; sk[r][c] = 0.f; sv[r][c] = 0.f;
    }
    if (tid < 196) {                       // sattn cols 52..55, rows 0..48
        sattn[tid >> 2][52 + (tid & 3)] = 0.f;
    }
    if (tid >= 196 && tid < 196 + 42) {    // sattn rows 49..51 (56 floats x3 /4)
        int t = tid - 196;
        *(float4*)&sattn[49 + t / 14][(t % 14) * 4] = make_float4(0, 0, 0, 0);
    }
    __syncthreads();

    float sc = __expf(fminf(logit_scale[h], 4.60517019f));

    for (int r = wid; r < NTOK; r += 8) {
        float qv = sq[r][lane];
        float s = qv * qv;
#pragma unroll
        for (int o = 16; o; o >>= 1) s += __shfl_xor_sync(0xffffffffu, s, o);
        sq[r][lane] = qv * rsqrtf(s + 1e-6f) * sc;
        float kv = sk[r][lane];
        float s2 = kv * kv;
#pragma unroll
        for (int o = 16; o; o >>= 1) s2 += __shfl_xor_sync(0xffffffffu, s2, o);
        sk[r][lane] = kv * rsqrtf(s2 + 1e-6f);
    }
    __syncthreads();

    // QK^T: 169 threads, j interleaved by 13 (conflict-free k loads),
    // accumulate into preloaded cbias via smem RMW.
    if (tid < 169) {
        int ti = tid / 13, tj = tid % 13;
        int i0 = 4 * ti;
        float a4[4][4];
#pragma unroll
        for (int u = 0; u < 4; ++u)
#pragma unroll
            for (int w = 0; w < 4; ++w) a4[u][w] = 0.f;
#pragma unroll
        for (int d = 0; d < HD; d += 4) {
            float4 qv[4], kv[4];
#pragma unroll
            for (int u = 0; u < 4; ++u) qv[u] = *(const float4*)&sq[i0 + u][d];
#pragma unroll
            for (int w = 0; w < 4; ++w) kv[w] = *(const float4*)&sk[tj + 13 * w][d];
#pragma unroll
            for (int u = 0; u < 4; ++u)
#pragma unroll
                for (int w = 0; w < 4; ++w) {
                    a4[u][w] = fmaf(qv[u].x, kv[w].x, a4[u][w]);
                    a4[u][w] = fmaf(qv[u].y, kv[w].y, a4[u][w]);
                    a4[u][w] = fmaf(qv[u].z, kv[w].z, a4[u][w]);
                    a4[u][w] = fmaf(qv[u].w, kv[w].w, a4[u][w]);
                }
        }
#pragma unroll
        for (int u = 0; u < 4; ++u) {
            int i = i0 + u;
            if (i < NTOK) {
#pragma unroll
                for (int w = 0; w < 4; ++w) {
                    int j = tj + 13 * w;
                    if (j < NTOK)
                        sattn[i][j] += a4[u][w];
                }
            }
        }
    }
    __syncthreads();

    for (int r = wid; r < NTOK; r += 8) {
        float v0 = sattn[r][lane];
        float v1 = (lane + 32 < NTOK) ? sattn[r][lane + 32] : -1e30f;
        float mx = fmaxf(v0, v1);
#pragma unroll
        for (int o = 16; o; o >>= 1) mx = fmaxf(mx, __shfl_xor_sync(0xffffffffu, mx, o));
        float e0 = __expf(v0 - mx);
        float e1 = (lane + 32 < NTOK) ? __expf(v1 - mx) : 0.f;
        float sm = e0 + e1;
#pragma unroll
        for (int o = 16; o; o >>= 1) sm += __shfl_xor_sync(0xffffffffu, sm, o);
        float inv = __fdividef(1.f, sm);
        sattn[r][lane] = e0 * inv;
        if (lane + 32 < NTOK) sattn[r][lane + 32] = e1 * inv;
    }
    __syncthreads();

    // out = attn @ v : 13 i-strips x 16 d-pairs (208 threads), float4 p loads
    if (tid < 208) {
        int ti = tid >> 4;            // 0..12
        int d0 = (tid & 15) * 2;      // 0,2,...,30
        int i0 = 4 * ti;
        float o0[4], o1[4];
#pragma unroll
        for (int u = 0; u < 4; ++u) { o0[u] = 0.f; o1[u] = 0.f; }
        for (int j4 = 0; j4 < 48; j4 += 4) {
            float pa[4][4];
#pragma unroll
            for (int u = 0; u < 4; ++u)
                *(float4*)pa[u] = *(const float4*)&sattn[i0 + u][j4];
#pragma unroll
            for (int jj = 0; jj < 4; ++jj) {
                float2 vv = *(const float2*)&sv[j4 + jj][d0];
                o0[0] = fmaf(pa[0][jj], vv.x, o0[0]); o1[0] = fmaf(pa[0][jj], vv.y, o1[0]);
                o0[1] = fmaf(pa[1][jj], vv.x, o0[1]); o1[1] = fmaf(pa[1][jj], vv.y, o1[1]);
                o0[2] = fmaf(pa[2][jj], vv.x, o0[2]); o1[2] = fmaf(pa[2][jj], vv.y, o1[2]);
                o0[3] = fmaf(pa[3][jj], vv.x, o0[3]); o1[3] = fmaf(pa[3][jj], vv.y, o1[3]);
            }
        }
        {   // tail j = 48
            float2 vv = *(const float2*)&sv[48][d0];
#pragma unroll
            for (int u = 0; u < 4; ++u) {
                float pu = sattn[i0 + u][48];
                o0[u] = fmaf(pu, vv.x, o0[u]);
                o1[u] = fmaf(pu, vv.y, o1[u]);
            }
        }
#pragma unroll
        for (int u = 0; u < 4; ++u) {
            int i = i0 + u;
            if (i < NTOK) {
                size_t idx = ((size_t)b * NTOK + i) * DIMC + h * HD + d0;
                __nv_bfloat16 h0 = __float2bfloat16(o0[u]);
                __nv_bfloat16 h1 = __float2bfloat16(o1[u]);
                *(uint32_t*)(g_aohi + idx) = pk(h0, h1);
                *(uint32_t*)(g_aolo + idx) =
                    pk(__float2bfloat16(o0[u] - __bfloat162float(h0)),
                       __float2bfloat16(o1[u] - __bfloat162float(h1)));
            }
        }
    }
}

// ---------------- launch ----------------
extern "C" void kernel_launch(void* const* d_in, const int* in_sizes, int n_in,
                              void* d_out, int out_size) {
    const float* x           = (const float*)d_in[0];
    const float* qkv_w       = (const float*)d_in[1];
    const float* q_bias      = (const float*)d_in[2];
    const float* v_bias      = (const float*)d_in[3];
    const float* logit_scale = (const float*)d_in[4];
    const float* cpb_w1      = (const float*)d_in[5];
    const float* cpb_b1      = (const float*)d_in[6];
    const float* cpb_w2      = (const float*)d_in[7];
    const float* coords      = (const float*)d_in[8];
    const int*   rpi         = (const int*)  d_in[9];
    const float* mask        = (const float*)d_in[10];
    const float* proj_w      = (const float*)d_in[11];
    const float* proj_b      = (const float*)d_in[12];
    float* out = (float*)d_out;

    float* qkv_ptr = nullptr; float* b768_ptr = nullptr;
    __nv_bfloat16 *xhi, *xlo, *aohi, *aolo, *wqhi, *wqlo, *wphi, *wplo;
    cudaGetSymbolAddress((void**)&qkv_ptr, g_qkv);
    cudaGetSymbolAddress((void**)&b768_ptr, g_bias768);
    cudaGetSymbolAddress((void**)&xhi, g_xhi);
    cudaGetSymbolAddress((void**)&xlo, g_xlo);
    cudaGetSymbolAddress((void**)&aohi, g_aohi);
    cudaGetSymbolAddress((void**)&aolo, g_aolo);
    cudaGetSymbolAddress((void**)&wqhi, g_wqhi);
    cudaGetSymbolAddress((void**)&wqlo, g_wqlo);
    cudaGetSymbolAddress((void**)&wphi, g_wphi);
    cudaGetSymbolAddress((void**)&wplo, g_wplo);

    cudaFuncSetAttribute(gemm_bf16x3,
                         cudaFuncAttributeMaxDynamicSharedMemorySize, GSMEM);

    // 1: all splits + bias fill
    split_all<<<(NTOT4 + 255) / 256, 256>>>(x, qkv_w, proj_w, q_bias, v_bias);
    // 2: CPB MLP + combined rpb/mask bias
    cbias_comb<<<64 * NH, 256>>>(rpi, mask, coords, cpb_w1, cpb_b1, cpb_w2);
    // 3: qkv GEMM
    gemm_bf16x3<<<dim3(TDIM / 128, MROWS / 128), 512, GSMEM>>>(
        xhi, xlo, wqhi, wqlo, b768_ptr, qkv_ptr, TDIM, DIMC);
    // 4 (profiled): attention
    attn_kernel<<<BWIN * NH, 256>>>(logit_scale);
    // 5: proj GEMM
    gemm_bf16x3<<<dim3(DIMC / 128, MROWS / 128), 512, GSMEM>>>(
        aohi, aolo, wphi, wplo, proj_b, out, DIMC, DIMC);
}

// round 15
// speedup vs baseline: 1.0176x; 1.0176x over previous
#include <cuda_runtime.h>
#include <cuda_bf16.h>
#include <math.h>
#include <stdint.h>
#include <stddef.h>

// ---------------- problem constants ----------------
#define BWIN   4096
#define NTOK   49
#define DIMC   256
#define NH     8
#define HD     32
#define TDIM   768
#define MROWS  (BWIN * NTOK)   // 200704

// ---------------- scratch ----------------
__device__ float g_qkv[(size_t)MROWS * TDIM];
__device__ __nv_bfloat16 g_xhi[(size_t)MROWS * DIMC];
__device__ __nv_bfloat16 g_xlo[(size_t)MROWS * DIMC];
__device__ __nv_bfloat16 g_aohi[(size_t)MROWS * DIMC];
__device__ __nv_bfloat16 g_aolo[(size_t)MROWS * DIMC];
__device__ __nv_bfloat16 g_wqhi[TDIM * DIMC];
__device__ __nv_bfloat16 g_wqlo[TDIM * DIMC];
__device__ __nv_bfloat16 g_wphi[DIMC * DIMC];
__device__ __nv_bfloat16 g_wplo[DIMC * DIMC];
__device__ float g_bias768[TDIM];
__device__ float g_cbias[64 * NH * 49 * 52];

__device__ __forceinline__ uint32_t pk(__nv_bfloat16 a, __nv_bfloat16 b) {
    return (uint32_t)__bfloat16_as_ushort(a) | ((uint32_t)__bfloat16_as_ushort(b) << 16);
}

__device__ __forceinline__ void split_store(const float* __restrict__ src,
                                            __nv_bfloat16* __restrict__ hi,
                                            __nv_bfloat16* __restrict__ lo, int i) {
    float4 v = ((const float4*)src)[i];
    __nv_bfloat16 hx = __float2bfloat16(v.x), hy = __float2bfloat16(v.y);
    __nv_bfloat16 hz = __float2bfloat16(v.z), hw = __float2bfloat16(v.w);
    uint2 H = make_uint2(pk(hx, hy), pk(hz, hw));
    uint2 L = make_uint2(
        pk(__float2bfloat16(v.x - __bfloat162float(hx)),
           __float2bfloat16(v.y - __bfloat162float(hy))),
        pk(__float2bfloat16(v.z - __bfloat162float(hz)),
           __float2bfloat16(v.w - __bfloat162float(hw))));
    ((uint2*)hi)[i] = H;
    ((uint2*)lo)[i] = L;
}

// ---------------- merged setup: split x/wq/wp + bias fill ----------------
#define NX4  (MROWS * DIMC / 4)
#define NWQ4 (TDIM * DIMC / 4)
#define NWP4 (DIMC * DIMC / 4)
#define NTOT4 (NX4 + NWQ4 + NWP4)

__global__ void split_all(const float* __restrict__ x,
                          const float* __restrict__ wq,
                          const float* __restrict__ wp,
                          const float* __restrict__ q_bias,
                          const float* __restrict__ v_bias) {
    int i = blockIdx.x * 256 + threadIdx.x;
    if (i < TDIM) {
        float bv;
        if (i < 256)      bv = q_bias[i];
        else if (i < 512) bv = 0.f;
        else              bv = v_bias[i - 512];
        g_bias768[i] = bv;
    }
    if (i < NX4) {
        split_store(x, g_xhi, g_xlo, i);
    } else if (i < NX4 + NWQ4) {
        split_store(wq, g_wqhi, g_wqlo, i - NX4);
    } else if (i < NTOT4) {
        split_store(wp, g_wphi, g_wplo, i - NX4 - NWQ4);
    }
}

// ---------------- merged CPB MLP + combined bias (per (wm,h) block) ----------
__global__ void cbias_comb(const int* __restrict__ rpi,
                           const float* __restrict__ mask,
                           const float* __restrict__ coords,
                           const float* __restrict__ w1,
                           const float* __restrict__ b1,
                           const float* __restrict__ w2) {
    __shared__ float th[169];
    int blk = blockIdx.x;            // wm*8 + h
    int wm = blk >> 3, h = blk & 7;
    int tid = threadIdx.x;
    if (tid < 169) {
        float c0 = coords[tid * 2 + 0];
        float c1 = coords[tid * 2 + 1];
        const float* w2h = w2 + h * 512;
        float s = 0.f;
        for (int k = 0; k < 512; ++k) {
            float v = fmaf(c0, w1[2 * k], fmaf(c1, w1[2 * k + 1], b1[k]));
            s = fmaf(fmaxf(v, 0.f), w2h[k], s);
        }
        th[tid] = s;
    }
    __syncthreads();
    float* dst = g_cbias + (size_t)blk * (49 * 52);
    const float* m = mask + wm * (NTOK * NTOK);
    for (int idx = tid; idx < 49 * 52; idx += 256) {
        int i = idx / 52, j = idx % 52;
        float v = 0.f;
        if (j < 49) {
            float t = th[rpi[i * NTOK + j]];
            v = 16.f / (1.f + expf(-t)) + m[i * NTOK + j];
        }
        dst[idx] = v;
    }
}

// ================= bf16x3 GEMM, 512 threads (4 warps/SMSP), KC=64 ===========
#define KC     64
#define ROWB   144
#define MATB   (128 * ROWB)
#define STAGEB (4 * MATB)
#define NSTG   3
#define GSMEM  (NSTG * STAGEB)

__device__ __forceinline__ uint32_t s2u(const void* p) {
    uint32_t a;
    asm("{ .reg .u64 t; cvta.to.shared.u64 t, %1; cvt.u32.u64 %0, t; }"
        : "=r"(a) : "l"(p));
    return a;
}

#define CPA16(saddr, gaddr)                                                   \
    asm volatile("cp.async.cg.shared.global [%0], [%1], 16;"                  \
                 :: "r"(saddr), "l"(gaddr))
#define CPA_COMMIT() asm volatile("cp.async.commit_group;" ::: "memory")
#define CPA_WAIT1()  asm volatile("cp.async.wait_group 1;" ::: "memory")

#define LDSM4(r0, r1, r2, r3, a)                                              \
    asm volatile("ldmatrix.sync.aligned.m8n8.x4.shared.b16 {%0,%1,%2,%3}, [%4];" \
                 : "=r"(r0), "=r"(r1), "=r"(r2), "=r"(r3) : "r"(a))

#define MMA16816(c, a, b)                                                     \
    asm volatile(                                                             \
        "mma.sync.aligned.m16n8k16.row.col.f32.bf16.bf16.f32 "                \
        "{%0,%1,%2,%3},{%4,%5,%6,%7},{%8,%9},{%0,%1,%2,%3};"                  \
        : "+f"((c)[0]), "+f"((c)[1]), "+f"((c)[2]), "+f"((c)[3])              \
        : "r"((a)[0]), "r"((a)[1]), "r"((a)[2]), "r"((a)[3]),                 \
          "r"((b)[0]), "r"((b)[1]))

__global__ __launch_bounds__(512)
void gemm_bf16x3(const __nv_bfloat16* __restrict__ Ahi,
                 const __nv_bfloat16* __restrict__ Alo,
                 const __nv_bfloat16* __restrict__ Whi,
                 const __nv_bfloat16* __restrict__ Wlo,
                 const float* __restrict__ bias, float* __restrict__ C,
                 int N, int K) {
    extern __shared__ char sm[];
    uint32_t smb = s2u(sm);

    int tid = threadIdx.x, lane = tid & 31, wid = tid >> 5;
    int warpM = wid & 3;
    int warpN = wid >> 2;
    size_t rowBlk = (size_t)blockIdx.y * 128;
    int colBlk = blockIdx.x * 128;

    float acc[2][4][4];
#pragma unroll
    for (int mt = 0; mt < 2; ++mt)
#pragma unroll
        for (int nt = 0; nt < 4; ++nt)
#pragma unroll
            for (int u = 0; u < 4; ++u) acc[mt][nt][u] = 0.f;

    const __nv_bfloat16* gA[2] = {Ahi, Alo};
    const __nv_bfloat16* gW[2] = {Whi, Wlo};

    const int NCH = K >> 6;

    int g = lane >> 3, l7 = lane & 7;
    uint32_t aOff = (uint32_t)(warpM * 32 + (g & 1) * 8 + l7) * ROWB + (uint32_t)(g >> 1) * 16;
    uint32_t wOff = (uint32_t)(warpN * 32 + (g >> 1) * 8 + l7) * ROWB + (uint32_t)(g & 1) * 16;

#define ISSUE_CHUNK(ch)                                                       \
    do {                                                                      \
        uint32_t stg_ = smb + (uint32_t)((ch) % 3) * STAGEB;                  \
        int koff_ = (ch) * KC;                                                \
        _Pragma("unroll")                                                     \
        for (int i_ = 0; i_ < 2; ++i_) {                                      \
            int slot_ = tid + i_ * 512;                                       \
            int lr_ = slot_ >> 3, lc_ = slot_ & 7;                            \
            uint32_t so_ = stg_ + (uint32_t)lr_ * ROWB + (uint32_t)lc_ * 16;  \
            size_t ge_ = (rowBlk + lr_) * (size_t)K + koff_ + lc_ * 8;        \
            size_t gw_ = (size_t)(colBlk + lr_) * K + koff_ + lc_ * 8;        \
            CPA16(so_,            gA[0] + ge_);                               \
            CPA16(so_ + MATB,     gA[1] + ge_);                               \
            CPA16(so_ + 2 * MATB, gW[0] + gw_);                               \
            CPA16(so_ + 3 * MATB, gW[1] + gw_);                               \
        }                                                                     \
    } while (0)

    uint32_t ah[2][2][4], al[2][2][4], wh[2][4][2], wl[2][4][2];

#define LOAD_FRAG(buf, stg, kb)                                               \
    do {                                                                      \
        _Pragma("unroll")                                                     \
        for (int mt_ = 0; mt_ < 2; ++mt_) {                                   \
            uint32_t ad_ = (stg) + aOff + (uint32_t)mt_ * (16 * ROWB) + (kb); \
            LDSM4(ah[buf][mt_][0], ah[buf][mt_][1], ah[buf][mt_][2], ah[buf][mt_][3], ad_); \
            LDSM4(al[buf][mt_][0], al[buf][mt_][1], al[buf][mt_][2], al[buf][mt_][3], ad_ + MATB); \
        }                                                                     \
        _Pragma("unroll")                                                     \
        for (int p_ = 0; p_ < 2; ++p_) {                                      \
            uint32_t wd_ = (stg) + 2 * MATB + wOff + (uint32_t)p_ * (16 * ROWB) + (kb); \
            uint32_t t0_, t1_, t2_, t3_;                                      \
            LDSM4(t0_, t1_, t2_, t3_, wd_);                                   \
            wh[buf][2 * p_][0] = t0_; wh[buf][2 * p_][1] = t1_;               \
            wh[buf][2 * p_ + 1][0] = t2_; wh[buf][2 * p_ + 1][1] = t3_;       \
            LDSM4(t0_, t1_, t2_, t3_, wd_ + MATB);                            \
            wl[buf][2 * p_][0] = t0_; wl[buf][2 * p_][1] = t1_;               \
            wl[buf][2 * p_ + 1][0] = t2_; wl[buf][2 * p_ + 1][1] = t3_;       \
        }                                                                     \
    } while (0)

#define MMA_STEP(buf)                                                         \
    do {                                                                      \
        _Pragma("unroll")                                                     \
        for (int mt_ = 0; mt_ < 2; ++mt_)                                     \
            _Pragma("unroll")                                                 \
            for (int nt_ = 0; nt_ < 4; ++nt_) {                               \
                MMA16816(acc[mt_][nt_], ah[buf][mt_], wh[buf][nt_]);          \
                MMA16816(acc[mt_][nt_], ah[buf][mt_], wl[buf][nt_]);          \
                MMA16816(acc[mt_][nt_], al[buf][mt_], wh[buf][nt_]);          \
            }                                                                 \
    } while (0)

    ISSUE_CHUNK(0); CPA_COMMIT();
    ISSUE_CHUNK(1); CPA_COMMIT();

    for (int ch = 0; ch < NCH; ++ch) {
        CPA_WAIT1();
        __syncthreads();
        if (ch + 2 < NCH) ISSUE_CHUNK(ch + 2);
        CPA_COMMIT();

        uint32_t stg = smb + (uint32_t)(ch % 3) * STAGEB;
        LOAD_FRAG(0, stg, 0u);
#pragma unroll
        for (int ks = 0; ks < 4; ++ks) {
            if (ks < 3) LOAD_FRAG((ks + 1) & 1, stg, (uint32_t)(ks + 1) * 32);
            MMA_STEP(ks & 1);
        }
    }

#pragma unroll
    for (int nt = 0; nt < 4; ++nt) {
        int col = colBlk + warpN * 32 + nt * 8 + (lane & 3) * 2;
        float2 bv = *(const float2*)(bias + col);
#pragma unroll
        for (int mt = 0; mt < 2; ++mt) {
            size_t row0 = rowBlk + warpM * 32 + mt * 16 + (lane >> 2);
            float2 o0, o1;
            o0.x = acc[mt][nt][0] + bv.x; o0.y = acc[mt][nt][1] + bv.y;
            o1.x = acc[mt][nt][2] + bv.x; o1.y = acc[mt][nt][3] + bv.y;
            *(float2*)(C + row0 * (size_t)N + col)       = o0;
            *(float2*)(C + (row0 + 8) * (size_t)N + col) = o1;
        }
    }
}

// ================= attention: R12 QK + float4 AV ============================
#define SAT 56   // sattn row stride (floats); float4-aligned at j%4==0

__global__ __launch_bounds__(256)
void attn_kernel(const float* __restrict__ logit_scale) {
    __shared__ float sq[52][36];
    __shared__ float sk[52][36];
    __shared__ float sv[52][36];
    __shared__ float sattn[52][SAT];

    int blk = blockIdx.x;
    int b = blk >> 3;
    int h = blk & 7;
    int tid = threadIdx.x;
    int wid = tid >> 5, lane = tid & 31;

    // load q,k,v (no pad zeroing: all pad reads feed guarded stores)
    for (int idx = tid; idx < NTOK * 8; idx += 256) {
        int n = idx >> 3, d4 = (idx & 7) << 2;
        size_t base = ((size_t)b * NTOK + n) * TDIM + h * HD + d4;
        *(float4*)&sq[n][d4] = *(const float4*)(g_qkv + base);
        *(float4*)&sk[n][d4] = *(const float4*)(g_qkv + base + 256);
        *(float4*)&sv[n][d4] = *(const float4*)(g_qkv + base + 512);
    }
    __syncthreads();

    float sc = __expf(fminf(logit_scale[h], 4.60517019f));

    for (int r = wid; r < NTOK; r += 8) {
        float qv = sq[r][lane];
        float s = qv * qv;
#pragma unroll
        for (int o = 16; o; o >>= 1) s += __shfl_xor_sync(0xffffffffu, s, o);
        sq[r][lane] = qv * rsqrtf(s + 1e-6f) * sc;
        float kv = sk[r][lane];
        float s2 = kv * kv;
#pragma unroll
        for (int o = 16; o; o >>= 1) s2 += __shfl_xor_sync(0xffffffffu, s2, o);
        sk[r][lane] = kv * rsqrtf(s2 + 1e-6f);
    }
    __syncthreads();

    // QK^T: 169 threads, j interleaved by 13 (conflict-free k loads),
    // cbias added via __ldg in the epilogue (latency hidden by store burst).
    if (tid < 169) {
        int ti = tid / 13, tj = tid % 13;
        int i0 = 4 * ti;
        float a4[4][4];
#pragma unroll
        for (int u = 0; u < 4; ++u)
#pragma unroll
            for (int w = 0; w < 4; ++w) a4[u][w] = 0.f;
#pragma unroll
        for (int d = 0; d < HD; d += 4) {
            float4 qv[4], kv[4];
#pragma unroll
            for (int u = 0; u < 4; ++u) qv[u] = *(const float4*)&sq[i0 + u][d];
#pragma unroll
            for (int w = 0; w < 4; ++w) kv[w] = *(const float4*)&sk[tj + 13 * w][d];
#pragma unroll
            for (int u = 0; u < 4; ++u)
#pragma unroll
                for (int w = 0; w < 4; ++w) {
                    a4[u][w] = fmaf(qv[u].x, kv[w].x, a4[u][w]);
                    a4[u][w] = fmaf(qv[u].y, kv[w].y, a4[u][w]);
                    a4[u][w] = fmaf(qv[u].z, kv[w].z, a4[u][w]);
                    a4[u][w] = fmaf(qv[u].w, kv[w].w, a4[u][w]);
                }
        }
        const float* cb = g_cbias + ((size_t)((b & 63) * NH + h)) * (49 * 52);
#pragma unroll
        for (int u = 0; u < 4; ++u) {
            int i = i0 + u;
            if (i < NTOK) {
#pragma unroll
                for (int w = 0; w < 4; ++w) {
                    int j = tj + 13 * w;
                    if (j < NTOK)
                        sattn[i][j] = a4[u][w] + __ldg(cb + i * 52 + j);
                }
            }
        }
    }
    __syncthreads();

    for (int r = wid; r < NTOK; r += 8) {
        float v0 = sattn[r][lane];
        float v1 = (lane + 32 < NTOK) ? sattn[r][lane + 32] : -1e30f;
        float mx = fmaxf(v0, v1);
#pragma unroll
        for (int o = 16; o; o >>= 1) mx = fmaxf(mx, __shfl_xor_sync(0xffffffffu, mx, o));
        float e0 = __expf(v0 - mx);
        float e1 = (lane + 32 < NTOK) ? __expf(v1 - mx) : 0.f;
        float sm = e0 + e1;
#pragma unroll
        for (int o = 16; o; o >>= 1) sm += __shfl_xor_sync(0xffffffffu, sm, o);
        float inv = __fdividef(1.f, sm);
        sattn[r][lane] = e0 * inv;
        if (lane + 32 < NTOK) sattn[r][lane + 32] = e1 * inv;
    }
    __syncthreads();

    // out = attn @ v : 13 i-strips x 16 d-pairs (208 threads), float4 p loads
    if (tid < 208) {
        int ti = tid >> 4;            // 0..12
        int d0 = (tid & 15) * 2;      // 0,2,...,30
        int i0 = 4 * ti;
        float o0[4], o1[4];
#pragma unroll
        for (int u = 0; u < 4; ++u) { o0[u] = 0.f; o1[u] = 0.f; }
        for (int j4 = 0; j4 < 48; j4 += 4) {
            float pa[4][4];
#pragma unroll
            for (int u = 0; u < 4; ++u)
                *(float4*)pa[u] = *(const float4*)&sattn[i0 + u][j4];
#pragma unroll
            for (int jj = 0; jj < 4; ++jj) {
                float2 vv = *(const float2*)&sv[j4 + jj][d0];
                o0[0] = fmaf(pa[0][jj], vv.x, o0[0]); o1[0] = fmaf(pa[0][jj], vv.y, o1[0]);
                o0[1] = fmaf(pa[1][jj], vv.x, o0[1]); o1[1] = fmaf(pa[1][jj], vv.y, o1[1]);
                o0[2] = fmaf(pa[2][jj], vv.x, o0[2]); o1[2] = fmaf(pa[2][jj], vv.y, o1[2]);
                o0[3] = fmaf(pa[3][jj], vv.x, o0[3]); o1[3] = fmaf(pa[3][jj], vv.y, o1[3]);
            }
        }
        {   // tail j = 48
            float2 vv = *(const float2*)&sv[48][d0];
#pragma unroll
            for (int u = 0; u < 4; ++u) {
                float pu = sattn[i0 + u][48];
                o0[u] = fmaf(pu, vv.x, o0[u]);
                o1[u] = fmaf(pu, vv.y, o1[u]);
            }
        }
#pragma unroll
        for (int u = 0; u < 4; ++u) {
            int i = i0 + u;
            if (i < NTOK) {
                size_t idx = ((size_t)b * NTOK + i) * DIMC + h * HD + d0;
                __nv_bfloat16 h0 = __float2bfloat16(o0[u]);
                __nv_bfloat16 h1 = __float2bfloat16(o1[u]);
                *(uint32_t*)(g_aohi + idx) = pk(h0, h1);
                *(uint32_t*)(g_aolo + idx) =
                    pk(__float2bfloat16(o0[u] - __bfloat162float(h0)),
                       __float2bfloat16(o1[u] - __bfloat162float(h1)));
            }
        }
    }
}

// ---------------- launch ----------------
extern "C" void kernel_launch(void* const* d_in, const int* in_sizes, int n_in,
                              void* d_out, int out_size) {
    const float* x           = (const float*)d_in[0];
    const float* qkv_w       = (const float*)d_in[1];
    const float* q_bias      = (const float*)d_in[2];
    const float* v_bias      = (const float*)d_in[3];
    const float* logit_scale = (const float*)d_in[4];
    const float* cpb_w1      = (const float*)d_in[5];
    const float* cpb_b1      = (const float*)d_in[6];
    const float* cpb_w2      = (const float*)d_in[7];
    const float* coords      = (const float*)d_in[8];
    const int*   rpi         = (const int*)  d_in[9];
    const float* mask        = (const float*)d_in[10];
    const float* proj_w      = (const float*)d_in[11];
    const float* proj_b      = (const float*)d_in[12];
    float* out = (float*)d_out;

    float* qkv_ptr = nullptr; float* b768_ptr = nullptr;
    __nv_bfloat16 *xhi, *xlo, *aohi, *aolo, *wqhi, *wqlo, *wphi, *wplo;
    cudaGetSymbolAddress((void**)&qkv_ptr, g_qkv);
    cudaGetSymbolAddress((void**)&b768_ptr, g_bias768);
    cudaGetSymbolAddress((void**)&xhi, g_xhi);
    cudaGetSymbolAddress((void**)&xlo, g_xlo);
    cudaGetSymbolAddress((void**)&aohi, g_aohi);
    cudaGetSymbolAddress((void**)&aolo, g_aolo);
    cudaGetSymbolAddress((void**)&wqhi, g_wqhi);
    cudaGetSymbolAddress((void**)&wqlo, g_wqlo);
    cudaGetSymbolAddress((void**)&wphi, g_wphi);
    cudaGetSymbolAddress((void**)&wplo, g_wplo);

    cudaFuncSetAttribute(gemm_bf16x3,
                         cudaFuncAttributeMaxDynamicSharedMemorySize, GSMEM);

    // 1: all splits + bias fill
    split_all<<<(NTOT4 + 255) / 256, 256>>>(x, qkv_w, proj_w, q_bias, v_bias);
    // 2: CPB MLP + combined rpb/mask bias
    cbias_comb<<<64 * NH, 256>>>(rpi, mask, coords, cpb_w1, cpb_b1, cpb_w2);
    // 3: qkv GEMM
    gemm_bf16x3<<<dim3(TDIM / 128, MROWS / 128), 512, GSMEM>>>(
        xhi, xlo, wqhi, wqlo, b768_ptr, qkv_ptr, TDIM, DIMC);
    // 4 (profiled): attention
    attn_kernel<<<BWIN * NH, 256>>>(logit_scale);
    // 5: proj GEMM
    gemm_bf16x3<<<dim3(DIMC / 128, MROWS / 128), 512, GSMEM>>>(
        aohi, aolo, wphi, wplo, proj_b, out, DIMC, DIMC);
}

// round 16
// speedup vs baseline: 1.0624x; 1.0440x over previous
#include <cuda_runtime.h>
#include <cuda_bf16.h>
#include <math.h>
#include <stdint.h>
#include <stddef.h>

// ---------------- problem constants ----------------
#define BWIN   4096
#define NTOK   49
#define DIMC   256
#define NH     8
#define HD     32
#define TDIM   768
#define MROWS  (BWIN * NTOK)   // 200704

// ---------------- scratch ----------------
__device__ float g_qkv[(size_t)MROWS * TDIM];
__device__ __nv_bfloat16 g_xhi[(size_t)MROWS * DIMC];
__device__ __nv_bfloat16 g_xlo[(size_t)MROWS * DIMC];
__device__ __nv_bfloat16 g_aohi[(size_t)MROWS * DIMC];
__device__ __nv_bfloat16 g_aolo[(size_t)MROWS * DIMC];
__device__ __nv_bfloat16 g_wqhi[TDIM * DIMC];
__device__ __nv_bfloat16 g_wqlo[TDIM * DIMC];
__device__ __nv_bfloat16 g_wphi[DIMC * DIMC];
__device__ __nv_bfloat16 g_wplo[DIMC * DIMC];
__device__ float g_bias768[TDIM];
__device__ float g_cbias[64 * NH * 49 * 52];

__device__ __forceinline__ uint32_t pk(__nv_bfloat16 a, __nv_bfloat16 b) {
    return (uint32_t)__bfloat16_as_ushort(a) | ((uint32_t)__bfloat16_as_ushort(b) << 16);
}

__device__ __forceinline__ void split_store(const float* __restrict__ src,
                                            __nv_bfloat16* __restrict__ hi,
                                            __nv_bfloat16* __restrict__ lo, int i) {
    float4 v = ((const float4*)src)[i];
    __nv_bfloat16 hx = __float2bfloat16(v.x), hy = __float2bfloat16(v.y);
    __nv_bfloat16 hz = __float2bfloat16(v.z), hw = __float2bfloat16(v.w);
    uint2 H = make_uint2(pk(hx, hy), pk(hz, hw));
    uint2 L = make_uint2(
        pk(__float2bfloat16(v.x - __bfloat162float(hx)),
           __float2bfloat16(v.y - __bfloat162float(hy))),
        pk(__float2bfloat16(v.z - __bfloat162float(hz)),
           __float2bfloat16(v.w - __bfloat162float(hw))));
    ((uint2*)hi)[i] = H;
    ((uint2*)lo)[i] = L;
}

// ---------------- merged setup: split x/wq/wp + bias fill ----------------
#define NX4  (MROWS * DIMC / 4)
#define NWQ4 (TDIM * DIMC / 4)
#define NWP4 (DIMC * DIMC / 4)
#define NTOT4 (NX4 + NWQ4 + NWP4)

__global__ void split_all(const float* __restrict__ x,
                          const float* __restrict__ wq,
                          const float* __restrict__ wp,
                          const float* __restrict__ q_bias,
                          const float* __restrict__ v_bias) {
    int i = blockIdx.x * 256 + threadIdx.x;
    if (i < TDIM) {
        float bv;
        if (i < 256)      bv = q_bias[i];
        else if (i < 512) bv = 0.f;
        else              bv = v_bias[i - 512];
        g_bias768[i] = bv;
    }
    if (i < NX4) {
        split_store(x, g_xhi, g_xlo, i);
    } else if (i < NX4 + NWQ4) {
        split_store(wq, g_wqhi, g_wqlo, i - NX4);
    } else if (i < NTOT4) {
        split_store(wp, g_wphi, g_wplo, i - NX4 - NWQ4);
    }
}

// ---------------- merged CPB MLP + combined bias (per (wm,h) block) ----------
__global__ void cbias_comb(const int* __restrict__ rpi,
                           const float* __restrict__ mask,
                           const float* __restrict__ coords,
                           const float* __restrict__ w1,
                           const float* __restrict__ b1,
                           const float* __restrict__ w2) {
    __shared__ float th[169];
    int blk = blockIdx.x;            // wm*8 + h
    int wm = blk >> 3, h = blk & 7;
    int tid = threadIdx.x;
    if (tid < 169) {
        float c0 = coords[tid * 2 + 0];
        float c1 = coords[tid * 2 + 1];
        const float* w2h = w2 + h * 512;
        float s = 0.f;
        for (int k = 0; k < 512; ++k) {
            float v = fmaf(c0, w1[2 * k], fmaf(c1, w1[2 * k + 1], b1[k]));
            s = fmaf(fmaxf(v, 0.f), w2h[k], s);
        }
        th[tid] = s;
    }
    __syncthreads();
    float* dst = g_cbias + (size_t)blk * (49 * 52);
    const float* m = mask + wm * (NTOK * NTOK);
    for (int idx = tid; idx < 49 * 52; idx += 256) {
        int i = idx / 52, j = idx % 52;
        float v = 0.f;
        if (j < 49) {
            float t = th[rpi[i * NTOK + j]];
            v = 16.f / (1.f + expf(-t)) + m[i * NTOK + j];
        }
        dst[idx] = v;
    }
}

// ================= bf16x3 GEMM, 512 threads (4 warps/SMSP), KC=64 ===========
#define KC     64
#define ROWB   144
#define MATB   (128 * ROWB)
#define STAGEB (4 * MATB)
#define NSTG   3
#define GSMEM  (NSTG * STAGEB)

__device__ __forceinline__ uint32_t s2u(const void* p) {
    uint32_t a;
    asm("{ .reg .u64 t; cvta.to.shared.u64 t, %1; cvt.u32.u64 %0, t; }"
        : "=r"(a) : "l"(p));
    return a;
}

#define CPA16(saddr, gaddr)                                                   \
    asm volatile("cp.async.cg.shared.global [%0], [%1], 16;"                  \
                 :: "r"(saddr), "l"(gaddr))
#define CPA_COMMIT() asm volatile("cp.async.commit_group;" ::: "memory")
#define CPA_WAIT1()  asm volatile("cp.async.wait_group 1;" ::: "memory")

#define LDSM4(r0, r1, r2, r3, a)                                              \
    asm volatile("ldmatrix.sync.aligned.m8n8.x4.shared.b16 {%0,%1,%2,%3}, [%4];" \
                 : "=r"(r0), "=r"(r1), "=r"(r2), "=r"(r3) : "r"(a))

#define MMA16816(c, a, b)                                                     \
    asm volatile(                                                             \
        "mma.sync.aligned.m16n8k16.row.col.f32.bf16.bf16.f32 "                \
        "{%0,%1,%2,%3},{%4,%5,%6,%7},{%8,%9},{%0,%1,%2,%3};"                  \
        : "+f"((c)[0]), "+f"((c)[1]), "+f"((c)[2]), "+f"((c)[3])              \
        : "r"((a)[0]), "r"((a)[1]), "r"((a)[2]), "r"((a)[3]),                 \
          "r"((b)[0]), "r"((b)[1]))

__global__ __launch_bounds__(512)
void gemm_bf16x3(const __nv_bfloat16* __restrict__ Ahi,
                 const __nv_bfloat16* __restrict__ Alo,
                 const __nv_bfloat16* __restrict__ Whi,
                 const __nv_bfloat16* __restrict__ Wlo,
                 const float* __restrict__ bias, float* __restrict__ C,
                 int N, int K) {
    extern __shared__ char sm[];
    uint32_t smb = s2u(sm);

    int tid = threadIdx.x, lane = tid & 31, wid = tid >> 5;
    int warpM = wid & 3;
    int warpN = wid >> 2;
    size_t rowBlk = (size_t)blockIdx.y * 128;
    int colBlk = blockIdx.x * 128;

    float acc[2][4][4];
#pragma unroll
    for (int mt = 0; mt < 2; ++mt)
#pragma unroll
        for (int nt = 0; nt < 4; ++nt)
#pragma unroll
            for (int u = 0; u < 4; ++u) acc[mt][nt][u] = 0.f;

    const __nv_bfloat16* gA[2] = {Ahi, Alo};
    const __nv_bfloat16* gW[2] = {Whi, Wlo};

    const int NCH = K >> 6;

    int g = lane >> 3, l7 = lane & 7;
    uint32_t aOff = (uint32_t)(warpM * 32 + (g & 1) * 8 + l7) * ROWB + (uint32_t)(g >> 1) * 16;
    uint32_t wOff = (uint32_t)(warpN * 32 + (g >> 1) * 8 + l7) * ROWB + (uint32_t)(g & 1) * 16;

#define ISSUE_CHUNK(ch)                                                       \
    do {                                                                      \
        uint32_t stg_ = smb + (uint32_t)((ch) % 3) * STAGEB;                  \
        int koff_ = (ch) * KC;                                                \
        _Pragma("unroll")                                                     \
        for (int i_ = 0; i_ < 2; ++i_) {                                      \
            int slot_ = tid + i_ * 512;                                       \
            int lr_ = slot_ >> 3, lc_ = slot_ & 7;                            \
            uint32_t so_ = stg_ + (uint32_t)lr_ * ROWB + (uint32_t)lc_ * 16;  \
            size_t ge_ = (rowBlk + lr_) * (size_t)K + koff_ + lc_ * 8;        \
            size_t gw_ = (size_t)(colBlk + lr_) * K + koff_ + lc_ * 8;        \
            CPA16(so_,            gA[0] + ge_);                               \
            CPA16(so_ + MATB,     gA[1] + ge_);                               \
            CPA16(so_ + 2 * MATB, gW[0] + gw_);                               \
            CPA16(so_ + 3 * MATB, gW[1] + gw_);                               \
        }                                                                     \
    } while (0)

    uint32_t ah[2][2][4], al[2][2][4], wh[2][4][2], wl[2][4][2];

#define LOAD_FRAG(buf, stg, kb)                                               \
    do {                                                                      \
        _Pragma("unroll")                                                     \
        for (int mt_ = 0; mt_ < 2; ++mt_) {                                   \
            uint32_t ad_ = (stg) + aOff + (uint32_t)mt_ * (16 * ROWB) + (kb); \
            LDSM4(ah[buf][mt_][0], ah[buf][mt_][1], ah[buf][mt_][2], ah[buf][mt_][3], ad_); \
            LDSM4(al[buf][mt_][0], al[buf][mt_][1], al[buf][mt_][2], al[buf][mt_][3], ad_ + MATB); \
        }                                                                     \
        _Pragma("unroll")                                                     \
        for (int p_ = 0; p_ < 2; ++p_) {                                      \
            uint32_t wd_ = (stg) + 2 * MATB + wOff + (uint32_t)p_ * (16 * ROWB) + (kb); \
            uint32_t t0_, t1_, t2_, t3_;                                      \
            LDSM4(t0_, t1_, t2_, t3_, wd_);                                   \
            wh[buf][2 * p_][0] = t0_; wh[buf][2 * p_][1] = t1_;               \
            wh[buf][2 * p_ + 1][0] = t2_; wh[buf][2 * p_ + 1][1] = t3_;       \
            LDSM4(t0_, t1_, t2_, t3_, wd_ + MATB);                            \
            wl[buf][2 * p_][0] = t0_; wl[buf][2 * p_][1] = t1_;               \
            wl[buf][2 * p_ + 1][0] = t2_; wl[buf][2 * p_ + 1][1] = t3_;       \
        }                                                                     \
    } while (0)

#define MMA_STEP(buf)                                                         \
    do {                                                                      \
        _Pragma("unroll")                                                     \
        for (int mt_ = 0; mt_ < 2; ++mt_)                                     \
            _Pragma("unroll")                                                 \
            for (int nt_ = 0; nt_ < 4; ++nt_) {                               \
                MMA16816(acc[mt_][nt_], ah[buf][mt_], wh[buf][nt_]);          \
                MMA16816(acc[mt_][nt_], ah[buf][mt_], wl[buf][nt_]);          \
                MMA16816(acc[mt_][nt_], al[buf][mt_], wh[buf][nt_]);          \
            }                                                                 \
    } while (0)

    ISSUE_CHUNK(0); CPA_COMMIT();
    ISSUE_CHUNK(1); CPA_COMMIT();

    for (int ch = 0; ch < NCH; ++ch) {
        CPA_WAIT1();
        __syncthreads();
        if (ch + 2 < NCH) ISSUE_CHUNK(ch + 2);
        CPA_COMMIT();

        uint32_t stg = smb + (uint32_t)(ch % 3) * STAGEB;
        LOAD_FRAG(0, stg, 0u);
#pragma unroll
        for (int ks = 0; ks < 4; ++ks) {
            if (ks < 3) LOAD_FRAG((ks + 1) & 1, stg, (uint32_t)(ks + 1) * 32);
            MMA_STEP(ks & 1);
        }
    }

#pragma unroll
    for (int nt = 0; nt < 4; ++nt) {
        int col = colBlk + warpN * 32 + nt * 8 + (lane & 3) * 2;
        float2 bv = *(const float2*)(bias + col);
#pragma unroll
        for (int mt = 0; mt < 2; ++mt) {
            size_t row0 = rowBlk + warpM * 32 + mt * 16 + (lane >> 2);
            float2 o0, o1;
            o0.x = acc[mt][nt][0] + bv.x; o0.y = acc[mt][nt][1] + bv.y;
            o1.x = acc[mt][nt][2] + bv.x; o1.y = acc[mt][nt][3] + bv.y;
            *(float2*)(C + row0 * (size_t)N + col)       = o0;
            *(float2*)(C + (row0 + 8) * (size_t)N + col) = o1;
        }
    }
}

// ===== attention: fused-norm loader + conflict-free QK + max-free softmax
//       + 104-thread float4 AV =====
#define SAT 52   // sattn row stride (floats), 16B-aligned float4 at j%4==0

__global__ __launch_bounds__(256)
void attn_kernel(const float* __restrict__ logit_scale) {
    __shared__ float sq[52][36];
    __shared__ float sk[52][36];
    __shared__ float sv[49][36];
    __shared__ float sattn[52][SAT];
    __shared__ float qn[52], kn[52];

    int blk = blockIdx.x;
    int b = blk >> 3;
    int h = blk & 7;
    int tid = threadIdx.x;
    int wid = tid >> 5, lane = tid & 31;

    float sc = __expf(fminf(logit_scale[h], 4.60517019f));

    // loader with fused row-norm factors: 8 consecutive threads own one row
    for (int base = 0; base < NTOK * 8; base += 256) {
        int idx = base + tid;
        bool act = idx < NTOK * 8;
        float sq_ = 0.f, sk_ = 0.f;
        int n = idx >> 3, d4 = (idx & 7) << 2;
        if (act) {
            size_t gbase = ((size_t)b * NTOK + n) * TDIM + h * HD + d4;
            float4 q = *(const float4*)(g_qkv + gbase);
            float4 k = *(const float4*)(g_qkv + gbase + 256);
            float4 v = *(const float4*)(g_qkv + gbase + 512);
            *(float4*)&sq[n][d4] = q;
            *(float4*)&sk[n][d4] = k;
            *(float4*)&sv[n][d4] = v;
            sq_ = q.x * q.x + q.y * q.y + q.z * q.z + q.w * q.w;
            sk_ = k.x * k.x + k.y * k.y + k.z * k.z + k.w * k.w;
        }
#pragma unroll
        for (int o = 4; o; o >>= 1) {
            sq_ += __shfl_xor_sync(0xffffffffu, sq_, o, 8);
            sk_ += __shfl_xor_sync(0xffffffffu, sk_, o, 8);
        }
        if (act && (idx & 7) == 0) {
            qn[n] = rsqrtf(sq_ + 1e-6f) * sc;
            kn[n] = rsqrtf(sk_ + 1e-6f);
        }
    }
    __syncthreads();

    // QK^T on raw q/k: 169 threads, j interleaved by 13 (conflict-free);
    // scale by qn[i]*kn[j] and add cbias (__ldg) in the epilogue.
    if (tid < 169) {
        int ti = tid / 13, tj = tid % 13;
        int i0 = 4 * ti;
        float a4[4][4];
#pragma unroll
        for (int u = 0; u < 4; ++u)
#pragma unroll
            for (int w = 0; w < 4; ++w) a4[u][w] = 0.f;
#pragma unroll
        for (int d = 0; d < HD; d += 4) {
            float4 qv[4], kv[4];
#pragma unroll
            for (int u = 0; u < 4; ++u) qv[u] = *(const float4*)&sq[i0 + u][d];
#pragma unroll
            for (int w = 0; w < 4; ++w) kv[w] = *(const float4*)&sk[tj + 13 * w][d];
#pragma unroll
            for (int u = 0; u < 4; ++u)
#pragma unroll
                for (int w = 0; w < 4; ++w) {
                    a4[u][w] = fmaf(qv[u].x, kv[w].x, a4[u][w]);
                    a4[u][w] = fmaf(qv[u].y, kv[w].y, a4[u][w]);
                    a4[u][w] = fmaf(qv[u].z, kv[w].z, a4[u][w]);
                    a4[u][w] = fmaf(qv[u].w, kv[w].w, a4[u][w]);
                }
        }
        const float* cb = g_cbias + ((size_t)((b & 63) * NH + h)) * (49 * 52);
#pragma unroll
        for (int u = 0; u < 4; ++u) {
            int i = i0 + u;
            if (i < NTOK) {
                float qi = qn[i];
#pragma unroll
                for (int w = 0; w < 4; ++w) {
                    int j = tj + 13 * w;
                    if (j < NTOK)
                        sattn[i][j] = a4[u][w] * qi * kn[j] + __ldg(cb + i * 52 + j);
                }
            }
        }
    }
    __syncthreads();

    // max-free softmax (logits bounded: scale<=100*|cos|+16, mask>=-100;
    // every row has an unmasked entry -> no overflow/degenerate sums here)
    for (int r = wid; r < NTOK; r += 8) {
        float e0 = __expf(sattn[r][lane]);
        float e1 = (lane + 32 < NTOK) ? __expf(sattn[r][lane + 32]) : 0.f;
        float sm = e0 + e1;
#pragma unroll
        for (int o = 16; o; o >>= 1) sm += __shfl_xor_sync(0xffffffffu, sm, o);
        float inv = __fdividef(1.f, sm);
        sattn[r][lane] = e0 * inv;
        if (lane + 32 < NTOK) sattn[r][lane + 32] = e1 * inv;
    }
    __syncthreads();

    // out = attn @ v : 13 i-strips x 8 d-quads (104 threads), float4 loads
    if (tid < 104) {
        int ti = tid >> 3;            // 0..12
        int d0 = (tid & 7) * 4;       // 0,4,...,28
        int i0 = 4 * ti;
        float acc[4][4];
#pragma unroll
        for (int u = 0; u < 4; ++u)
#pragma unroll
            for (int c = 0; c < 4; ++c) acc[u][c] = 0.f;
        for (int j4 = 0; j4 < 48; j4 += 4) {
            float4 pa[4], vv[4];
#pragma unroll
            for (int u = 0; u < 4; ++u)
                pa[u] = *(const float4*)&sattn[i0 + u][j4];
#pragma unroll
            for (int jj = 0; jj < 4; ++jj)
                vv[jj] = *(const float4*)&sv[j4 + jj][d0];
#pragma unroll
            for (int u = 0; u < 4; ++u) {
                acc[u][0] = fmaf(pa[u].x, vv[0].x, acc[u][0]);
                acc[u][1] = fmaf(pa[u].x, vv[0].y, acc[u][1]);
                acc[u][2] = fmaf(pa[u].x, vv[0].z, acc[u][2]);
                acc[u][3] = fmaf(pa[u].x, vv[0].w, acc[u][3]);
                acc[u][0] = fmaf(pa[u].y, vv[1].x, acc[u][0]);
                acc[u][1] = fmaf(pa[u].y, vv[1].y, acc[u][1]);
                acc[u][2] = fmaf(pa[u].y, vv[1].z, acc[u][2]);
                acc[u][3] = fmaf(pa[u].y, vv[1].w, acc[u][3]);
                acc[u][0] = fmaf(pa[u].z, vv[2].x, acc[u][0]);
                acc[u][1] = fmaf(pa[u].z, vv[2].y, acc[u][1]);
                acc[u][2] = fmaf(pa[u].z, vv[2].z, acc[u][2]);
                acc[u][3] = fmaf(pa[u].z, vv[2].w, acc[u][3]);
                acc[u][0] = fmaf(pa[u].w, vv[3].x, acc[u][0]);
                acc[u][1] = fmaf(pa[u].w, vv[3].y, acc[u][1]);
                acc[u][2] = fmaf(pa[u].w, vv[3].z, acc[u][2]);
                acc[u][3] = fmaf(pa[u].w, vv[3].w, acc[u][3]);
            }
        }
        {   // tail j = 48
            float4 v48 = *(const float4*)&sv[48][d0];
#pragma unroll
            for (int u = 0; u < 4; ++u) {
                float pu = sattn[i0 + u][48];
                acc[u][0] = fmaf(pu, v48.x, acc[u][0]);
                acc[u][1] = fmaf(pu, v48.y, acc[u][1]);
                acc[u][2] = fmaf(pu, v48.z, acc[u][2]);
                acc[u][3] = fmaf(pu, v48.w, acc[u][3]);
            }
        }
#pragma unroll
        for (int u = 0; u < 4; ++u) {
            int i = i0 + u;
            if (i < NTOK) {
                size_t idx = ((size_t)b * NTOK + i) * DIMC + h * HD + d0;
                __nv_bfloat16 h0 = __float2bfloat16(acc[u][0]);
                __nv_bfloat16 h1 = __float2bfloat16(acc[u][1]);
                __nv_bfloat16 h2 = __float2bfloat16(acc[u][2]);
                __nv_bfloat16 h3 = __float2bfloat16(acc[u][3]);
                uint2 H = make_uint2(pk(h0, h1), pk(h2, h3));
                uint2 L = make_uint2(
                    pk(__float2bfloat16(acc[u][0] - __bfloat162float(h0)),
                       __float2bfloat16(acc[u][1] - __bfloat162float(h1))),
                    pk(__float2bfloat16(acc[u][2] - __bfloat162float(h2)),
                       __float2bfloat16(acc[u][3] - __bfloat162float(h3))));
                *(uint2*)(g_aohi + idx) = H;
                *(uint2*)(g_aolo + idx) = L;
            }
        }
    }
}

// ---------------- launch ----------------
extern "C" void kernel_launch(void* const* d_in, const int* in_sizes, int n_in,
                              void* d_out, int out_size) {
    const float* x           = (const float*)d_in[0];
    const float* qkv_w       = (const float*)d_in[1];
    const float* q_bias      = (const float*)d_in[2];
    const float* v_bias      = (const float*)d_in[3];
    const float* logit_scale = (const float*)d_in[4];
    const float* cpb_w1      = (const float*)d_in[5];
    const float* cpb_b1      = (const float*)d_in[6];
    const float* cpb_w2      = (const float*)d_in[7];
    const float* coords      = (const float*)d_in[8];
    const int*   rpi         = (const int*)  d_in[9];
    const float* mask        = (const float*)d_in[10];
    const float* proj_w      = (const float*)d_in[11];
    const float* proj_b      = (const float*)d_in[12];
    float* out = (float*)d_out;

    float* qkv_ptr = nullptr; float* b768_ptr = nullptr;
    __nv_bfloat16 *xhi, *xlo, *aohi, *aolo, *wqhi, *wqlo, *wphi, *wplo;
    cudaGetSymbolAddress((void**)&qkv_ptr, g_qkv);
    cudaGetSymbolAddress((void**)&b768_ptr, g_bias768);
    cudaGetSymbolAddress((void**)&xhi, g_xhi);
    cudaGetSymbolAddress((void**)&xlo, g_xlo);
    cudaGetSymbolAddress((void**)&aohi, g_aohi);
    cudaGetSymbolAddress((void**)&aolo, g_aolo);
    cudaGetSymbolAddress((void**)&wqhi, g_wqhi);
    cudaGetSymbolAddress((void**)&wqlo, g_wqlo);
    cudaGetSymbolAddress((void**)&wphi, g_wphi);
    cudaGetSymbolAddress((void**)&wplo, g_wplo);

    cudaFuncSetAttribute(gemm_bf16x3,
                         cudaFuncAttributeMaxDynamicSharedMemorySize, GSMEM);

    // 1: all splits + bias fill
    split_all<<<(NTOT4 + 255) / 256, 256>>>(x, qkv_w, proj_w, q_bias, v_bias);
    // 2: CPB MLP + combined rpb/mask bias
    cbias_comb<<<64 * NH, 256>>>(rpi, mask, coords, cpb_w1, cpb_b1, cpb_w2);
    // 3: qkv GEMM
    gemm_bf16x3<<<dim3(TDIM / 128, MROWS / 128), 512, GSMEM>>>(
        xhi, xlo, wqhi, wqlo, b768_ptr, qkv_ptr, TDIM, DIMC);
    // 4 (profiled): attention
    attn_kernel<<<BWIN * NH, 256>>>(logit_scale);
    // 5: proj GEMM
    gemm_bf16x3<<<dim3(DIMC / 128, MROWS / 128), 512, GSMEM>>>(
        aohi, aolo, wphi, wplo, proj_b, out, DIMC, DIMC);
}

// round 17
// speedup vs baseline: 1.0624x; 1.0001x over previous
#include <cuda_runtime.h>
#include <cuda_bf16.h>
#include <math.h>
#include <stdint.h>
#include <stddef.h>

// ---------------- problem constants ----------------
#define BWIN   4096
#define NTOK   49
#define DIMC   256
#define NH     8
#define HD     32
#define TDIM   768
#define MROWS  (BWIN * NTOK)   // 200704

// ---------------- scratch ----------------
__device__ float g_qkv[(size_t)MROWS * TDIM];
__device__ __nv_bfloat16 g_xhi[(size_t)MROWS * DIMC];
__device__ __nv_bfloat16 g_xlo[(size_t)MROWS * DIMC];
__device__ __nv_bfloat16 g_aohi[(size_t)MROWS * DIMC];
__device__ __nv_bfloat16 g_aolo[(size_t)MROWS * DIMC];
__device__ __nv_bfloat16 g_wqhi[TDIM * DIMC];
__device__ __nv_bfloat16 g_wqlo[TDIM * DIMC];
__device__ __nv_bfloat16 g_wphi[DIMC * DIMC];
__device__ __nv_bfloat16 g_wplo[DIMC * DIMC];
__device__ float g_bias768[TDIM];
__device__ float g_cbias[64 * NH * 49 * 52];

__device__ __forceinline__ uint32_t pk(__nv_bfloat16 a, __nv_bfloat16 b) {
    return (uint32_t)__bfloat16_as_ushort(a) | ((uint32_t)__bfloat16_as_ushort(b) << 16);
}

__device__ __forceinline__ void split_store(const float* __restrict__ src,
                                            __nv_bfloat16* __restrict__ hi,
                                            __nv_bfloat16* __restrict__ lo, int i) {
    float4 v = ((const float4*)src)[i];
    __nv_bfloat16 hx = __float2bfloat16(v.x), hy = __float2bfloat16(v.y);
    __nv_bfloat16 hz = __float2bfloat16(v.z), hw = __float2bfloat16(v.w);
    uint2 H = make_uint2(pk(hx, hy), pk(hz, hw));
    uint2 L = make_uint2(
        pk(__float2bfloat16(v.x - __bfloat162float(hx)),
           __float2bfloat16(v.y - __bfloat162float(hy))),
        pk(__float2bfloat16(v.z - __bfloat162float(hz)),
           __float2bfloat16(v.w - __bfloat162float(hw))));
    ((uint2*)hi)[i] = H;
    ((uint2*)lo)[i] = L;
}

// ---------------- merged setup: split x/wq/wp + bias fill ----------------
#define NX4  (MROWS * DIMC / 4)
#define NWQ4 (TDIM * DIMC / 4)
#define NWP4 (DIMC * DIMC / 4)
#define NTOT4 (NX4 + NWQ4 + NWP4)

__global__ void split_all(const float* __restrict__ x,
                          const float* __restrict__ wq,
                          const float* __restrict__ wp,
                          const float* __restrict__ q_bias,
                          const float* __restrict__ v_bias) {
    int i = blockIdx.x * 256 + threadIdx.x;
    if (i < TDIM) {
        float bv;
        if (i < 256)      bv = q_bias[i];
        else if (i < 512) bv = 0.f;
        else              bv = v_bias[i - 512];
        g_bias768[i] = bv;
    }
    if (i < NX4) {
        split_store(x, g_xhi, g_xlo, i);
    } else if (i < NX4 + NWQ4) {
        split_store(wq, g_wqhi, g_wqlo, i - NX4);
    } else if (i < NTOT4) {
        split_store(wp, g_wphi, g_wplo, i - NX4 - NWQ4);
    }
}

// ---------------- merged CPB MLP + combined bias (per (wm,h) block) ----------
__global__ void cbias_comb(const int* __restrict__ rpi,
                           const float* __restrict__ mask,
                           const float* __restrict__ coords,
                           const float* __restrict__ w1,
                           const float* __restrict__ b1,
                           const float* __restrict__ w2) {
    __shared__ float th[169];
    int blk = blockIdx.x;            // wm*8 + h
    int wm = blk >> 3, h = blk & 7;
    int tid = threadIdx.x;
    if (tid < 169) {
        float c0 = coords[tid * 2 + 0];
        float c1 = coords[tid * 2 + 1];
        const float* w2h = w2 + h * 512;
        float s = 0.f;
        for (int k = 0; k < 512; ++k) {
            float v = fmaf(c0, w1[2 * k], fmaf(c1, w1[2 * k + 1], b1[k]));
            s = fmaf(fmaxf(v, 0.f), w2h[k], s);
        }
        th[tid] = s;
    }
    __syncthreads();
    float* dst = g_cbias + (size_t)blk * (49 * 52);
    const float* m = mask + wm * (NTOK * NTOK);
    for (int idx = tid; idx < 49 * 52; idx += 256) {
        int i = idx / 52, j = idx % 52;
        float v = 0.f;
        if (j < 49) {
            float t = th[rpi[i * NTOK + j]];
            v = 16.f / (1.f + expf(-t)) + m[i * NTOK + j];
        }
        dst[idx] = v;
    }
}

// ================= bf16x3 GEMM, 512 threads, KC=64, term-major MMA order ====
#define KC     64
#define ROWB   144
#define MATB   (128 * ROWB)
#define STAGEB (4 * MATB)
#define NSTG   3
#define GSMEM  (NSTG * STAGEB)

__device__ __forceinline__ uint32_t s2u(const void* p) {
    uint32_t a;
    asm("{ .reg .u64 t; cvta.to.shared.u64 t, %1; cvt.u32.u64 %0, t; }"
        : "=r"(a) : "l"(p));
    return a;
}

#define CPA16(saddr, gaddr)                                                   \
    asm volatile("cp.async.cg.shared.global [%0], [%1], 16;"                  \
                 :: "r"(saddr), "l"(gaddr))
#define CPA_COMMIT() asm volatile("cp.async.commit_group;" ::: "memory")
#define CPA_WAIT1()  asm volatile("cp.async.wait_group 1;" ::: "memory")

#define LDSM4(r0, r1, r2, r3, a)                                              \
    asm volatile("ldmatrix.sync.aligned.m8n8.x4.shared.b16 {%0,%1,%2,%3}, [%4];" \
                 : "=r"(r0), "=r"(r1), "=r"(r2), "=r"(r3) : "r"(a))

#define MMA16816(c, a, b)                                                     \
    asm volatile(                                                             \
        "mma.sync.aligned.m16n8k16.row.col.f32.bf16.bf16.f32 "                \
        "{%0,%1,%2,%3},{%4,%5,%6,%7},{%8,%9},{%0,%1,%2,%3};"                  \
        : "+f"((c)[0]), "+f"((c)[1]), "+f"((c)[2]), "+f"((c)[3])              \
        : "r"((a)[0]), "r"((a)[1]), "r"((a)[2]), "r"((a)[3]),                 \
          "r"((b)[0]), "r"((b)[1]))

__global__ __launch_bounds__(512)
void gemm_bf16x3(const __nv_bfloat16* __restrict__ Ahi,
                 const __nv_bfloat16* __restrict__ Alo,
                 const __nv_bfloat16* __restrict__ Whi,
                 const __nv_bfloat16* __restrict__ Wlo,
                 const float* __restrict__ bias, float* __restrict__ C,
                 int N, int K) {
    extern __shared__ char sm[];
    uint32_t smb = s2u(sm);

    int tid = threadIdx.x, lane = tid & 31, wid = tid >> 5;
    int warpM = wid & 3;
    int warpN = wid >> 2;
    size_t rowBlk = (size_t)blockIdx.y * 128;
    int colBlk = blockIdx.x * 128;

    float acc[2][4][4];
#pragma unroll
    for (int mt = 0; mt < 2; ++mt)
#pragma unroll
        for (int nt = 0; nt < 4; ++nt)
#pragma unroll
            for (int u = 0; u < 4; ++u) acc[mt][nt][u] = 0.f;

    const __nv_bfloat16* gA[2] = {Ahi, Alo};
    const __nv_bfloat16* gW[2] = {Whi, Wlo};

    const int NCH = K >> 6;

    int g = lane >> 3, l7 = lane & 7;
    uint32_t aOff = (uint32_t)(warpM * 32 + (g & 1) * 8 + l7) * ROWB + (uint32_t)(g >> 1) * 16;
    uint32_t wOff = (uint32_t)(warpN * 32 + (g >> 1) * 8 + l7) * ROWB + (uint32_t)(g & 1) * 16;

#define ISSUE_CHUNK(ch)                                                       \
    do {                                                                      \
        uint32_t stg_ = smb + (uint32_t)((ch) % 3) * STAGEB;                  \
        int koff_ = (ch) * KC;                                                \
        _Pragma("unroll")                                                     \
        for (int i_ = 0; i_ < 2; ++i_) {                                      \
            int slot_ = tid + i_ * 512;                                       \
            int lr_ = slot_ >> 3, lc_ = slot_ & 7;                            \
            uint32_t so_ = stg_ + (uint32_t)lr_ * ROWB + (uint32_t)lc_ * 16;  \
            size_t ge_ = (rowBlk + lr_) * (size_t)K + koff_ + lc_ * 8;        \
            size_t gw_ = (size_t)(colBlk + lr_) * K + koff_ + lc_ * 8;        \
            CPA16(so_,            gA[0] + ge_);                               \
            CPA16(so_ + MATB,     gA[1] + ge_);                               \
            CPA16(so_ + 2 * MATB, gW[0] + gw_);                               \
            CPA16(so_ + 3 * MATB, gW[1] + gw_);                               \
        }                                                                     \
    } while (0)

    uint32_t ah[2][2][4], al[2][2][4], wh[2][4][2], wl[2][4][2];

#define LOAD_FRAG(buf, stg, kb)                                               \
    do {                                                                      \
        _Pragma("unroll")                                                     \
        for (int mt_ = 0; mt_ < 2; ++mt_) {                                   \
            uint32_t ad_ = (stg) + aOff + (uint32_t)mt_ * (16 * ROWB) + (kb); \
            LDSM4(ah[buf][mt_][0], ah[buf][mt_][1], ah[buf][mt_][2], ah[buf][mt_][3], ad_); \
            LDSM4(al[buf][mt_][0], al[buf][mt_][1], al[buf][mt_][2], al[buf][mt_][3], ad_ + MATB); \
        }                                                                     \
        _Pragma("unroll")                                                     \
        for (int p_ = 0; p_ < 2; ++p_) {                                      \
            uint32_t wd_ = (stg) + 2 * MATB + wOff + (uint32_t)p_ * (16 * ROWB) + (kb); \
            uint32_t t0_, t1_, t2_, t3_;                                      \
            LDSM4(t0_, t1_, t2_, t3_, wd_);                                   \
            wh[buf][2 * p_][0] = t0_; wh[buf][2 * p_][1] = t1_;               \
            wh[buf][2 * p_ + 1][0] = t2_; wh[buf][2 * p_ + 1][1] = t3_;       \
            LDSM4(t0_, t1_, t2_, t3_, wd_ + MATB);                            \
            wl[buf][2 * p_][0] = t0_; wl[buf][2 * p_][1] = t1_;               \
            wl[buf][2 * p_ + 1][0] = t2_; wl[buf][2 * p_ + 1][1] = t3_;       \
        }                                                                     \
    } while (0)

// term-major order: all 8 independent accumulators between same-acc reuses
#define MMA_STEP(buf)                                                         \
    do {                                                                      \
        _Pragma("unroll")                                                     \
        for (int mt_ = 0; mt_ < 2; ++mt_)                                     \
            _Pragma("unroll")                                                 \
            for (int nt_ = 0; nt_ < 4; ++nt_)                                 \
                MMA16816(acc[mt_][nt_], ah[buf][mt_], wh[buf][nt_]);          \
        _Pragma("unroll")                                                     \
        for (int mt_ = 0; mt_ < 2; ++mt_)                                     \
            _Pragma("unroll")                                                 \
            for (int nt_ = 0; nt_ < 4; ++nt_)                                 \
                MMA16816(acc[mt_][nt_], ah[buf][mt_], wl[buf][nt_]);          \
        _Pragma("unroll")                                                     \
        for (int mt_ = 0; mt_ < 2; ++mt_)                                     \
            _Pragma("unroll")                                                 \
            for (int nt_ = 0; nt_ < 4; ++nt_)                                 \
                MMA16816(acc[mt_][nt_], al[buf][mt_], wh[buf][nt_]);          \
    } while (0)

    ISSUE_CHUNK(0); CPA_COMMIT();
    ISSUE_CHUNK(1); CPA_COMMIT();

    for (int ch = 0; ch < NCH; ++ch) {
        CPA_WAIT1();
        __syncthreads();
        if (ch + 2 < NCH) ISSUE_CHUNK(ch + 2);
        CPA_COMMIT();

        uint32_t stg = smb + (uint32_t)(ch % 3) * STAGEB;
        LOAD_FRAG(0, stg, 0u);
#pragma unroll
        for (int ks = 0; ks < 4; ++ks) {
            if (ks < 3) LOAD_FRAG((ks + 1) & 1, stg, (uint32_t)(ks + 1) * 32);
            MMA_STEP(ks & 1);
        }
    }

#pragma unroll
    for (int nt = 0; nt < 4; ++nt) {
        int col = colBlk + warpN * 32 + nt * 8 + (lane & 3) * 2;
        float2 bv = *(const float2*)(bias + col);
#pragma unroll
        for (int mt = 0; mt < 2; ++mt) {
            size_t row0 = rowBlk + warpM * 32 + mt * 16 + (lane >> 2);
            float2 o0, o1;
            o0.x = acc[mt][nt][0] + bv.x; o0.y = acc[mt][nt][1] + bv.y;
            o1.x = acc[mt][nt][2] + bv.x; o1.y = acc[mt][nt][3] + bv.y;
            *(float2*)(C + row0 * (size_t)N + col)       = o0;
            *(float2*)(C + (row0 + 8) * (size_t)N + col) = o1;
        }
    }
}

// ===== attention (R16 proven): fused-norm loader + conflict-free QK +
//       max-free softmax + 104-thread float4 AV =====
#define SAT 52

__global__ __launch_bounds__(256)
void attn_kernel(const float* __restrict__ logit_scale) {
    __shared__ float sq[52][36];
    __shared__ float sk[52][36];
    __shared__ float sv[49][36];
    __shared__ float sattn[52][SAT];
    __shared__ float qn[52], kn[52];

    int blk = blockIdx.x;
    int b = blk >> 3;
    int h = blk & 7;
    int tid = threadIdx.x;
    int wid = tid >> 5, lane = tid & 31;

    float sc = __expf(fminf(logit_scale[h], 4.60517019f));

    for (int base = 0; base < NTOK * 8; base += 256) {
        int idx = base + tid;
        bool act = idx < NTOK * 8;
        float sq_ = 0.f, sk_ = 0.f;
        int n = idx >> 3, d4 = (idx & 7) << 2;
        if (act) {
            size_t gbase = ((size_t)b * NTOK + n) * TDIM + h * HD + d4;
            float4 q = *(const float4*)(g_qkv + gbase);
            float4 k = *(const float4*)(g_qkv + gbase + 256);
            float4 v = *(const float4*)(g_qkv + gbase + 512);
            *(float4*)&sq[n][d4] = q;
            *(float4*)&sk[n][d4] = k;
            *(float4*)&sv[n][d4] = v;
            sq_ = q.x * q.x + q.y * q.y + q.z * q.z + q.w * q.w;
            sk_ = k.x * k.x + k.y * k.y + k.z * k.z + k.w * k.w;
        }
#pragma unroll
        for (int o = 4; o; o >>= 1) {
            sq_ += __shfl_xor_sync(0xffffffffu, sq_, o, 8);
            sk_ += __shfl_xor_sync(0xffffffffu, sk_, o, 8);
        }
        if (act && (idx & 7) == 0) {
            qn[n] = rsqrtf(sq_ + 1e-6f) * sc;
            kn[n] = rsqrtf(sk_ + 1e-6f);
        }
    }
    __syncthreads();

    if (tid < 169) {
        int ti = tid / 13, tj = tid % 13;
        int i0 = 4 * ti;
        float a4[4][4];
#pragma unroll
        for (int u = 0; u < 4; ++u)
#pragma unroll
            for (int w = 0; w < 4; ++w) a4[u][w] = 0.f;
#pragma unroll
        for (int d = 0; d < HD; d += 4) {
            float4 qv[4], kv[4];
#pragma unroll
            for (int u = 0; u < 4; ++u) qv[u] = *(const float4*)&sq[i0 + u][d];
#pragma unroll
            for (int w = 0; w < 4; ++w) kv[w] = *(const float4*)&sk[tj + 13 * w][d];
#pragma unroll
            for (int u = 0; u < 4; ++u)
#pragma unroll
                for (int w = 0; w < 4; ++w) {
                    a4[u][w] = fmaf(qv[u].x, kv[w].x, a4[u][w]);
                    a4[u][w] = fmaf(qv[u].y, kv[w].y, a4[u][w]);
                    a4[u][w] = fmaf(qv[u].z, kv[w].z, a4[u][w]);
                    a4[u][w] = fmaf(qv[u].w, kv[w].w, a4[u][w]);
                }
        }
        const float* cb = g_cbias + ((size_t)((b & 63) * NH + h)) * (49 * 52);
#pragma unroll
        for (int u = 0; u < 4; ++u) {
            int i = i0 + u;
            if (i < NTOK) {
                float qi = qn[i];
#pragma unroll
                for (int w = 0; w < 4; ++w) {
                    int j = tj + 13 * w;
                    if (j < NTOK)
                        sattn[i][j] = a4[u][w] * qi * kn[j] + __ldg(cb + i * 52 + j);
                }
            }
        }
    }
    __syncthreads();

    for (int r = wid; r < NTOK; r += 8) {
        float e0 = __expf(sattn[r][lane]);
        float e1 = (lane + 32 < NTOK) ? __expf(sattn[r][lane + 32]) : 0.f;
        float sm = e0 + e1;
#pragma unroll
        for (int o = 16; o; o >>= 1) sm += __shfl_xor_sync(0xffffffffu, sm, o);
        float inv = __fdividef(1.f, sm);
        sattn[r][lane] = e0 * inv;
        if (lane + 32 < NTOK) sattn[r][lane + 32] = e1 * inv;
    }
    __syncthreads();

    if (tid < 104) {
        int ti = tid >> 3;
        int d0 = (tid & 7) * 4;
        int i0 = 4 * ti;
        float acc[4][4];
#pragma unroll
        for (int u = 0; u < 4; ++u)
#pragma unroll
            for (int c = 0; c < 4; ++c) acc[u][c] = 0.f;
        for (int j4 = 0; j4 < 48; j4 += 4) {
            float4 pa[4], vv[4];
#pragma unroll
            for (int u = 0; u < 4; ++u)
                pa[u] = *(const float4*)&sattn[i0 + u][j4];
#pragma unroll
            for (int jj = 0; jj < 4; ++jj)
                vv[jj] = *(const float4*)&sv[j4 + jj][d0];
#pragma unroll
            for (int u = 0; u < 4; ++u) {
                acc[u][0] = fmaf(pa[u].x, vv[0].x, acc[u][0]);
                acc[u][1] = fmaf(pa[u].x, vv[0].y, acc[u][1]);
                acc[u][2] = fmaf(pa[u].x, vv[0].z, acc[u][2]);
                acc[u][3] = fmaf(pa[u].x, vv[0].w, acc[u][3]);
                acc[u][0] = fmaf(pa[u].y, vv[1].x, acc[u][0]);
                acc[u][1] = fmaf(pa[u].y, vv[1].y, acc[u][1]);
                acc[u][2] = fmaf(pa[u].y, vv[1].z, acc[u][2]);
                acc[u][3] = fmaf(pa[u].y, vv[1].w, acc[u][3]);
                acc[u][0] = fmaf(pa[u].z, vv[2].x, acc[u][0]);
                acc[u][1] = fmaf(pa[u].z, vv[2].y, acc[u][1]);
                acc[u][2] = fmaf(pa[u].z, vv[2].z, acc[u][2]);
                acc[u][3] = fmaf(pa[u].z, vv[2].w, acc[u][3]);
                acc[u][0] = fmaf(pa[u].w, vv[3].x, acc[u][0]);
                acc[u][1] = fmaf(pa[u].w, vv[3].y, acc[u][1]);
                acc[u][2] = fmaf(pa[u].w, vv[3].z, acc[u][2]);
                acc[u][3] = fmaf(pa[u].w, vv[3].w, acc[u][3]);
            }
        }
        {
            float4 v48 = *(const float4*)&sv[48][d0];
#pragma unroll
            for (int u = 0; u < 4; ++u) {
                float pu = sattn[i0 + u][48];
                acc[u][0] = fmaf(pu, v48.x, acc[u][0]);
                acc[u][1] = fmaf(pu, v48.y, acc[u][1]);
                acc[u][2] = fmaf(pu, v48.z, acc[u][2]);
                acc[u][3] = fmaf(pu, v48.w, acc[u][3]);
            }
        }
#pragma unroll
        for (int u = 0; u < 4; ++u) {
            int i = i0 + u;
            if (i < NTOK) {
                size_t idx = ((size_t)b * NTOK + i) * DIMC + h * HD + d0;
                __nv_bfloat16 h0 = __float2bfloat16(acc[u][0]);
                __nv_bfloat16 h1 = __float2bfloat16(acc[u][1]);
                __nv_bfloat16 h2 = __float2bfloat16(acc[u][2]);
                __nv_bfloat16 h3 = __float2bfloat16(acc[u][3]);
                uint2 H = make_uint2(pk(h0, h1), pk(h2, h3));
                uint2 L = make_uint2(
                    pk(__float2bfloat16(acc[u][0] - __bfloat162float(h0)),
                       __float2bfloat16(acc[u][1] - __bfloat162float(h1))),
                    pk(__float2bfloat16(acc[u][2] - __bfloat162float(h2)),
                       __float2bfloat16(acc[u][3] - __bfloat162float(h3))));
                *(uint2*)(g_aohi + idx) = H;
                *(uint2*)(g_aolo + idx) = L;
            }
        }
    }
}

// ---------------- launch ----------------
extern "C" void kernel_launch(void* const* d_in, const int* in_sizes, int n_in,
                              void* d_out, int out_size) {
    const float* x           = (const float*)d_in[0];
    const float* qkv_w       = (const float*)d_in[1];
    const float* q_bias      = (const float*)d_in[2];
    const float* v_bias      = (const float*)d_in[3];
    const float* logit_scale = (const float*)d_in[4];
    const float* cpb_w1      = (const float*)d_in[5];
    const float* cpb_b1      = (const float*)d_in[6];
    const float* cpb_w2      = (const float*)d_in[7];
    const float* coords      = (const float*)d_in[8];
    const int*   rpi         = (const int*)  d_in[9];
    const float* mask        = (const float*)d_in[10];
    const float* proj_w      = (const float*)d_in[11];
    const float* proj_b      = (const float*)d_in[12];
    float* out = (float*)d_out;

    float* qkv_ptr = nullptr; float* b768_ptr = nullptr;
    __nv_bfloat16 *xhi, *xlo, *aohi, *aolo, *wqhi, *wqlo, *wphi, *wplo;
    cudaGetSymbolAddress((void**)&qkv_ptr, g_qkv);
    cudaGetSymbolAddress((void**)&b768_ptr, g_bias768);
    cudaGetSymbolAddress((void**)&xhi, g_xhi);
    cudaGetSymbolAddress((void**)&xlo, g_xlo);
    cudaGetSymbolAddress((void**)&aohi, g_aohi);
    cudaGetSymbolAddress((void**)&aolo, g_aolo);
    cudaGetSymbolAddress((void**)&wqhi, g_wqhi);
    cudaGetSymbolAddress((void**)&wqlo, g_wqlo);
    cudaGetSymbolAddress((void**)&wphi, g_wphi);
    cudaGetSymbolAddress((void**)&wplo, g_wplo);

    cudaFuncSetAttribute(gemm_bf16x3,
                         cudaFuncAttributeMaxDynamicSharedMemorySize, GSMEM);

    // 1: all splits + bias fill
    split_all<<<(NTOT4 + 255) / 256, 256>>>(x, qkv_w, proj_w, q_bias, v_bias);
    // 2: CPB MLP + combined rpb/mask bias
    cbias_comb<<<64 * NH, 256>>>(rpi, mask, coords, cpb_w1, cpb_b1, cpb_w2);
    // 3: qkv GEMM
    gemm_bf16x3<<<dim3(TDIM / 128, MROWS / 128), 512, GSMEM>>>(
        xhi, xlo, wqhi, wqlo, b768_ptr, qkv_ptr, TDIM, DIMC);
    // 4 (profiled): attention
    attn_kernel<<<BWIN * NH, 256>>>(logit_scale);
    // 5: proj GEMM
    gemm_bf16x3<<<dim3(DIMC / 128, MROWS / 128), 512, GSMEM>>>(
        aohi, aolo, wphi, wplo, proj_b, out, DIMC, DIMC);
}